// round 7
// baseline (speedup 1.0000x reference)
#include <cuda_runtime.h>
#include <cuda_bf16.h>

// CubEcc2d: Euler characteristic curve of sublevel cubical complex.
// x: [B=32, C=16, H=128, W=128] f32  ->  out: [B,C,RES=64] f32
//
// R7: fused kernel; lower-star body (validated R5). float4 row loads + shfl.
// i8 histogram, one byte slot per (thread, sub-column): byte = bin*512+4*tid+k
// -> race-free, bank-conflict-free, 4 independent RMW chains per thread.
// dp4a reduce; last-arriving block per image scans + writes out.

#define NT 128
#define RES 64
#define STRIPS 4

__device__ __align__(16) int g_part[512 * RES * STRIPS];  // [img][bin][strip]
__device__ int g_count[512];                              // zero-init; reset each run

#define INFB 0x7f800000

struct RowR { float4 q; float le, re; };

__device__ __forceinline__ RowR load_row(const float4* __restrict__ rp, int lane)
{
    RowR R;
    R.q  = rp[lane];
    R.le = __shfl_up_sync(0xffffffffu, R.q.w, 1);
    R.re = __shfl_down_sync(0xffffffffu, R.q.x, 1);
    if (lane == 0)  R.le = __int_as_float(INFB);
    if (lane == 31) R.re = __int_as_float(INFB);
    return R;
}

__device__ __forceinline__ RowR inf_row()
{
    RowR R;
    float inf = __int_as_float(INFB);
    R.q = make_float4(inf, inf, inf, inf);
    R.le = inf; R.re = inf;
    return R;
}

// One vertex: claim incident cells under total order (value, linear index).
// Earlier-index neighbors (prev row, left) use <=, later use <.
// Non-negative floats (or +INF) -> int compare == float compare.
__device__ __forceinline__ void vert(signed char* __restrict__ h,
    float pl, float pv, float pr,
    float l,  float v,  float r,
    float nl, float nv, float nr)
{
    const int iv  = __float_as_int(v);
    const int bl  = __float_as_int(l)  <= iv;
    const int bu  = __float_as_int(pv) <= iv;
    const int bul = __float_as_int(pl) <= iv;
    const int bur = __float_as_int(pr) <= iv;
    const int br  = __float_as_int(r)  <  iv;
    const int bnl = __float_as_int(nl) <  iv;
    const int bnv = __float_as_int(nv) <  iv;
    const int bnr = __float_as_int(nr) <  iv;

    int s = 1 - bl - br - bu - bnv
          + (bul & bu & bl)            // NW face
          + (bu & bur & br)            // NE face
          + (bl & bnl & bnv)           // SW face
          + (br & bnv & bnr);          // SE face

    int t = min(63, __float2int_ru(v * 63.0f));
    h[t << 9] = (signed char)(h[t << 9] + s);   // byte slot: bin*512 (+ base 4*tid+k)
}

__device__ __forceinline__ void do_row(const RowR& P, const RowR& C, const RowR& N,
    signed char* __restrict__ h0, signed char* __restrict__ h1,
    signed char* __restrict__ h2, signed char* __restrict__ h3)
{
    vert(h0, P.le,  P.q.x, P.q.y,  C.le,  C.q.x, C.q.y,  N.le,  N.q.x, N.q.y);
    vert(h1, P.q.x, P.q.y, P.q.z,  C.q.x, C.q.y, C.q.z,  N.q.x, N.q.y, N.q.z);
    vert(h2, P.q.y, P.q.z, P.q.w,  C.q.y, C.q.z, C.q.w,  N.q.y, N.q.z, N.q.w);
    vert(h3, P.q.z, P.q.w, P.re,   C.q.z, C.q.w, C.re,   N.q.z, N.q.w, N.re);
}

__global__ __launch_bounds__(NT, 7)
void ecc_kernel(const float* __restrict__ x, float* __restrict__ out)
{
    __shared__ signed char hist8[RES * 512];   // 32 KB, byte = bin*512 + 4*tid + k
    __shared__ int s_red[NT];
    __shared__ int s_last;

    const int tid  = threadIdx.x;
    const int lane = tid & 31;
    const int wid  = tid >> 5;

    {   // zero 32 KB = 2048 int4
        int4* z = (int4*)hist8;
        #pragma unroll
        for (int i = 0; i < 16; i++) z[tid + i * NT] = make_int4(0, 0, 0, 0);
    }
    __syncthreads();

    const int img   = blockIdx.x >> 2;
    const int strip = blockIdx.x & 3;
    const int band  = strip * 32 + wid * 8;     // first body row for this warp
    const float4* __restrict__ im4 = (const float4*)(x + (size_t)img * 16384);

    // 4 private byte slots per thread; word = bin*128 + tid -> bank = lane
    signed char* const hb = hist8 + 4 * tid;
    signed char* const h0 = hb;
    signed char* const h1 = hb + 1;
    signed char* const h2 = hb + 2;
    signed char* const h3 = hb + 3;

    RowR P = (band == 0) ? inf_row() : load_row(im4 + (band - 1) * 32, lane);
    RowR C = load_row(im4 + band * 32, lane);

    #pragma unroll 2
    for (int i = 0; i < 8; i++) {
        const int a = band + i;
        RowR N = (a == 127) ? inf_row() : load_row(im4 + (a + 1) * 32, lane);
        do_row(P, C, N, h0, h1, h2, h3);
        P = C; C = N;
    }
    __syncthreads();

    // reduce: 512 i8 slots -> bin total via dp4a over 128 words (skewed)
    {
        const int bin = tid & 63;
        const int p   = tid >> 6;
        const int* __restrict__ row = (const int*)hist8 + (bin << 7) + (p << 6);
        int sum = 0;
        #pragma unroll 8
        for (int i = 0; i < 64; i++)
            sum = __dp4a(row[(i + bin) & 63], 0x01010101, sum);
        s_red[tid] = sum;
    }
    __syncthreads();
    if (tid < RES)
        g_part[img * (RES * STRIPS) + (tid << 2) + strip] = s_red[tid] + s_red[tid + 64];

    // ---- last block of this image combines, scans, writes out ----
    if (tid == 0) {
        __threadfence();
        int old = atomicAdd(&g_count[img], 1);
        s_last = (old == STRIPS - 1) ? 1 : 0;
    }
    __syncthreads();

    if (s_last && wid == 0) {
        __threadfence();   // acquire other strips' g_part writes
        const int4* gp = (const int4*)g_part + img * RES;
        int4 p0 = gp[lane];          // bin = lane,    strips 0..3
        int4 p1 = gp[lane + 32];     // bin = lane+32
        int a  = p0.x + p0.y + p0.z + p0.w;
        int b2 = p1.x + p1.y + p1.z + p1.w;

        #pragma unroll
        for (int s = 1; s < 32; s <<= 1) {
            int n = __shfl_up_sync(0xffffffffu, a, s);
            if (lane >= s) a += n;
        }
        #pragma unroll
        for (int s = 1; s < 32; s <<= 1) {
            int n = __shfl_up_sync(0xffffffffu, b2, s);
            if (lane >= s) b2 += n;
        }
        b2 += __shfl_sync(0xffffffffu, a, 31);

        out[img * RES + lane]      = (float)a;
        out[img * RES + 32 + lane] = (float)b2;

        if (lane == 0) g_count[img] = 0;   // reset for next graph replay
    }
}

extern "C" void kernel_launch(void* const* d_in, const int* in_sizes, int n_in,
                              void* d_out, int out_size)
{
    const float* x = (const float*)d_in[0];
    float* out = (float*)d_out;
    ecc_kernel<<<512 * STRIPS, NT>>>(x, out);
}

// round 8
// speedup vs baseline: 1.1871x; 1.1871x over previous
#include <cuda_runtime.h>
#include <cuda_bf16.h>

// CubEcc2d: Euler characteristic curve of sublevel cubical complex.
// x: [B=32, C=16, H=128, W=128] f32  ->  out: [B,C,RES=64] f32
//
// R8: fused kernel, lower-star (1 RMW per vertex). Edge-shared comparisons:
// each lattice edge is compared once at its later endpoint; the earlier
// endpoint reuses the complement (carried across rows / sub-columns).
// 16KB i8 histogram, slot byte = bin*256 + 4*(lane+32k) + wid: race-free,
// bank-conflict-free, 2 independent RMW chains/thread. dp4a reduce; last
// strip-block per image scans + writes out.

#define NT 128
#define RES 64
#define STRIPS 4
#define INFB 0x7f800000

__device__ __align__(16) int g_part[512 * RES * STRIPS];  // [img][bin][strip]
__device__ int g_count[512];                              // zero-init; reset each run

struct RowR { float4 q; float le, re; };

__device__ __forceinline__ RowR load_row(const float4* __restrict__ rp, int lane)
{
    RowR R;
    R.q  = rp[lane];
    R.le = __shfl_up_sync(0xffffffffu, R.q.w, 1);
    R.re = __shfl_down_sync(0xffffffffu, R.q.x, 1);
    if (lane == 0)  R.le = __int_as_float(INFB);
    if (lane == 31) R.re = __int_as_float(INFB);
    return R;
}

__device__ __forceinline__ RowR inf_row()
{
    RowR R;
    float inf = __int_as_float(INFB);
    R.q = make_float4(inf, inf, inf, inf);
    R.le = inf; R.re = inf;
    return R;
}

__device__ __forceinline__ int fci(float f) { return __float_as_int(f); }

__device__ __forceinline__ int binof(float v)
{
    return min(63, __float2int_ru(v * 63.0f));
}

__global__ __launch_bounds__(NT, 10)
void ecc_kernel(const float* __restrict__ x, float* __restrict__ out)
{
    __shared__ signed char hist8[RES * 256];   // 16 KB
    __shared__ int s_red[NT];
    __shared__ int s_last;

    const int tid  = threadIdx.x;
    const int lane = tid & 31;
    const int wid  = tid >> 5;

    {   // zero 16 KB = 1024 int4
        int4* z = (int4*)hist8;
        #pragma unroll
        for (int i = 0; i < 8; i++) z[tid + i * NT] = make_int4(0, 0, 0, 0);
    }
    __syncthreads();

    const int img   = blockIdx.x >> 2;
    const int strip = blockIdx.x & 3;
    const int band  = strip * 32 + wid * 8;
    const float4* __restrict__ im4 = (const float4*)(x + (size_t)img * 16384);

    // chain bases: unique byte per (lane, wid, k); bank = lane for both chains
    signed char* const h0 = hist8 + 4 * lane + wid;          // sub-cols 0,1
    signed char* const h1 = hist8 + 4 * (lane + 32) + wid;   // sub-cols 2,3

    RowR P = (band == 0) ? inf_row() : load_row(im4 + (band - 1) * 32, lane);
    RowR C = load_row(im4 + band * 32, lane);

    // carried "later" comparisons from the P->C edge layer
    // pbnl[k] = (C[k-1] < P[k]), pbnv[k] = (C[k] < P[k]), pbnr[k] = (C[k+1] < P[k])
    int pbnl1 = fci(C.q.x) < fci(P.q.y);
    int pbnl2 = fci(C.q.y) < fci(P.q.z);
    int pbnl3 = fci(C.q.z) < fci(P.q.w);
    int pbnv0 = fci(C.q.x) < fci(P.q.x);
    int pbnv1 = fci(C.q.y) < fci(P.q.y);
    int pbnv2 = fci(C.q.z) < fci(P.q.z);
    int pbnv3 = fci(C.q.w) < fci(P.q.w);
    int pbnr0 = fci(C.q.y) < fci(P.q.x);
    int pbnr1 = fci(C.q.z) < fci(P.q.y);
    int pbnr2 = fci(C.q.w) < fci(P.q.z);
    float ple = P.le, pre = P.re;

    #pragma unroll
    for (int i = 0; i < 8; i++) {
        const int a = band + i;
        RowR N = (a == 127) ? inf_row() : load_row(im4 + (a + 1) * 32, lane);

        const int iv0 = fci(C.q.x), iv1 = fci(C.q.y);
        const int iv2 = fci(C.q.z), iv3 = fci(C.q.w);
        const int inl = fci(N.le), in0 = fci(N.q.x), in1 = fci(N.q.y);
        const int in2 = fci(N.q.z), in3 = fci(N.q.w), inr = fci(N.re);

        // same-row horizontal edges (later endpoint computes)
        const int br0 = iv1 < iv0, br1 = iv2 < iv1, br2 = iv3 < iv2;
        const int br3 = fci(C.re) < iv3;
        const int bl0 = fci(C.le) <= iv0;
        const int bl1 = 1 - br0, bl2 = 1 - br1, bl3 = 1 - br2;

        // carried vertical/diagonal edges (complement of prev row's compares)
        const int bu0 = 1 - pbnv0, bu1 = 1 - pbnv1, bu2 = 1 - pbnv2, bu3 = 1 - pbnv3;
        const int bul0 = fci(ple) <= iv0;
        const int bul1 = 1 - pbnr0, bul2 = 1 - pbnr1, bul3 = 1 - pbnr2;
        const int bur0 = 1 - pbnl1, bur1 = 1 - pbnl2, bur2 = 1 - pbnl3;
        const int bur3 = fci(pre) <= iv3;

        // fresh next-row edges
        const int bnl0 = inl < iv0, bnl1 = in0 < iv1, bnl2 = in1 < iv2, bnl3 = in2 < iv3;
        const int bnv0 = in0 < iv0, bnv1 = in1 < iv1, bnv2 = in2 < iv2, bnv3 = in3 < iv3;
        const int bnr0 = in1 < iv0, bnr1 = in2 < iv1, bnr2 = in3 < iv2, bnr3 = inr < iv3;

        const int s0 = 1 - bl0 - br0 - bu0 - bnv0
                     + (bul0 & bu0 & bl0) + (bu0 & bur0 & br0)
                     + (bl0 & bnl0 & bnv0) + (br0 & bnv0 & bnr0);
        const int s1 = 1 - bl1 - br1 - bu1 - bnv1
                     + (bul1 & bu1 & bl1) + (bu1 & bur1 & br1)
                     + (bl1 & bnl1 & bnv1) + (br1 & bnv1 & bnr1);
        const int s2 = 1 - bl2 - br2 - bu2 - bnv2
                     + (bul2 & bu2 & bl2) + (bu2 & bur2 & br2)
                     + (bl2 & bnl2 & bnv2) + (br2 & bnv2 & bnr2);
        const int s3 = 1 - bl3 - br3 - bu3 - bnv3
                     + (bul3 & bu3 & bl3) + (bu3 & bur3 & br3)
                     + (bl3 & bnl3 & bnv3) + (br3 & bnv3 & bnr3);

        const int t0 = binof(C.q.x), t1 = binof(C.q.y);
        const int t2 = binof(C.q.z), t3 = binof(C.q.w);

        h0[t0 << 8] = (signed char)(h0[t0 << 8] + s0);
        h1[t2 << 8] = (signed char)(h1[t2 << 8] + s2);
        h0[t1 << 8] = (signed char)(h0[t1 << 8] + s1);
        h1[t3 << 8] = (signed char)(h1[t3 << 8] + s3);

        // carry for next row
        pbnl1 = bnl1; pbnl2 = bnl2; pbnl3 = bnl3;
        pbnv0 = bnv0; pbnv1 = bnv1; pbnv2 = bnv2; pbnv3 = bnv3;
        pbnr0 = bnr0; pbnr1 = bnr1; pbnr2 = bnr2;
        ple = C.le; pre = C.re;
        C = N;
    }
    __syncthreads();

    // reduce: 256 i8 slots/bin -> total via dp4a over 64 words (skewed)
    {
        const int bin = tid & 63;
        const int p   = tid >> 6;
        const int* __restrict__ row = (const int*)hist8 + (bin << 6) + (p << 5);
        int sum = 0;
        #pragma unroll 8
        for (int i = 0; i < 32; i++)
            sum = __dp4a(row[(i + bin) & 31], 0x01010101, sum);
        s_red[tid] = sum;
    }
    __syncthreads();
    if (tid < RES)
        g_part[img * (RES * STRIPS) + (tid << 2) + strip] = s_red[tid] + s_red[tid + 64];

    // ---- last block of this image combines, scans, writes out ----
    if (tid == 0) {
        __threadfence();
        int old = atomicAdd(&g_count[img], 1);
        s_last = (old == STRIPS - 1) ? 1 : 0;
    }
    __syncthreads();

    if (s_last && wid == 0) {
        __threadfence();
        const int4* gp = (const int4*)g_part + img * RES;
        int4 p0 = gp[lane];
        int4 p1 = gp[lane + 32];
        int acc = p0.x + p0.y + p0.z + p0.w;
        int b2  = p1.x + p1.y + p1.z + p1.w;

        #pragma unroll
        for (int s = 1; s < 32; s <<= 1) {
            int n = __shfl_up_sync(0xffffffffu, acc, s);
            if (lane >= s) acc += n;
        }
        #pragma unroll
        for (int s = 1; s < 32; s <<= 1) {
            int n = __shfl_up_sync(0xffffffffu, b2, s);
            if (lane >= s) b2 += n;
        }
        b2 += __shfl_sync(0xffffffffu, acc, 31);

        out[img * RES + lane]      = (float)acc;
        out[img * RES + 32 + lane] = (float)b2;

        if (lane == 0) g_count[img] = 0;
    }
}

extern "C" void kernel_launch(void* const* d_in, const int* in_sizes, int n_in,
                              void* d_out, int out_size)
{
    const float* x = (const float*)d_in[0];
    float* out = (float*)d_out;
    ecc_kernel<<<512 * STRIPS, NT>>>(x, out);
}

// round 9
// speedup vs baseline: 1.2924x; 1.0886x over previous
#include <cuda_runtime.h>
#include <cuda_bf16.h>

// CubEcc2d: Euler characteristic curve of sublevel cubical complex.
// x: [B=32, C=16, H=128, W=128] f32  ->  out: [B,C,RES=64] f32
//
// R9: R8 structure (edge-shared lower-star, 16KB byte-slot histogram, fused
// final) with pipe rebalancing: comparisons done as FLOAT compares (FSETP on
// the fma pipe, identical semantics for nonneg/+INF values) instead of int
// ISETP on the saturated alu pipe; min(63,·) dropped (input < 1 => bin <= 63).

#define NT 128
#define RES 64
#define STRIPS 4
#define INFB 0x7f800000

__device__ __align__(16) int g_part[512 * RES * STRIPS];  // [img][bin][strip]
__device__ int g_count[512];                              // zero-init; reset each run

struct RowR { float4 q; float le, re; };

__device__ __forceinline__ RowR load_row(const float4* __restrict__ rp, int lane)
{
    RowR R;
    R.q  = rp[lane];
    R.le = __shfl_up_sync(0xffffffffu, R.q.w, 1);
    R.re = __shfl_down_sync(0xffffffffu, R.q.x, 1);
    if (lane == 0)  R.le = __int_as_float(INFB);
    if (lane == 31) R.re = __int_as_float(INFB);
    return R;
}

__device__ __forceinline__ RowR inf_row()
{
    RowR R;
    float inf = __int_as_float(INFB);
    R.q = make_float4(inf, inf, inf, inf);
    R.le = inf; R.re = inf;
    return R;
}

__device__ __forceinline__ int binof(float v)
{
    return __float2int_ru(v * 63.0f);    // v in [0,1) -> 0..63, no clamp needed
}

__global__ __launch_bounds__(NT, 10)
void ecc_kernel(const float* __restrict__ x, float* __restrict__ out)
{
    __shared__ signed char hist8[RES * 256];   // 16 KB
    __shared__ int s_red[NT];
    __shared__ int s_last;

    const int tid  = threadIdx.x;
    const int lane = tid & 31;
    const int wid  = tid >> 5;

    {   // zero 16 KB = 1024 int4
        int4* z = (int4*)hist8;
        #pragma unroll
        for (int i = 0; i < 8; i++) z[tid + i * NT] = make_int4(0, 0, 0, 0);
    }
    __syncthreads();

    const int img   = blockIdx.x >> 2;
    const int strip = blockIdx.x & 3;
    const int band  = strip * 32 + wid * 8;
    const float4* __restrict__ im4 = (const float4*)(x + (size_t)img * 16384);

    // chain bases: unique byte per (lane, wid, k); bank = lane for both chains
    signed char* const h0 = hist8 + 4 * lane + wid;          // sub-cols 0,1
    signed char* const h1 = hist8 + 4 * (lane + 32) + wid;   // sub-cols 2,3

    RowR P = (band == 0) ? inf_row() : load_row(im4 + (band - 1) * 32, lane);
    RowR C = load_row(im4 + band * 32, lane);

    // carried "later" comparisons from the P->C edge layer (float compares;
    // identical to int compares for nonneg/+INF values)
    int pbnl1 = C.q.x < P.q.y;
    int pbnl2 = C.q.y < P.q.z;
    int pbnl3 = C.q.z < P.q.w;
    int pbnv0 = C.q.x < P.q.x;
    int pbnv1 = C.q.y < P.q.y;
    int pbnv2 = C.q.z < P.q.z;
    int pbnv3 = C.q.w < P.q.w;
    int pbnr0 = C.q.y < P.q.x;
    int pbnr1 = C.q.z < P.q.y;
    int pbnr2 = C.q.w < P.q.z;
    float ple = P.le, pre = P.re;

    #pragma unroll
    for (int i = 0; i < 8; i++) {
        const int a = band + i;
        RowR N = (a == 127) ? inf_row() : load_row(im4 + (a + 1) * 32, lane);

        // same-row horizontal edges (later endpoint computes)
        const int br0 = C.q.y < C.q.x, br1 = C.q.z < C.q.y, br2 = C.q.w < C.q.z;
        const int br3 = C.re  < C.q.w;
        const int bl0 = C.le <= C.q.x;
        const int bl1 = 1 - br0, bl2 = 1 - br1, bl3 = 1 - br2;

        // carried vertical/diagonal edges (complement of prev row's compares)
        const int bu0 = 1 - pbnv0, bu1 = 1 - pbnv1, bu2 = 1 - pbnv2, bu3 = 1 - pbnv3;
        const int bul0 = ple <= C.q.x;
        const int bul1 = 1 - pbnr0, bul2 = 1 - pbnr1, bul3 = 1 - pbnr2;
        const int bur0 = 1 - pbnl1, bur1 = 1 - pbnl2, bur2 = 1 - pbnl3;
        const int bur3 = pre <= C.q.w;

        // fresh next-row edges
        const int bnl0 = N.le  < C.q.x, bnl1 = N.q.x < C.q.y;
        const int bnl2 = N.q.y < C.q.z, bnl3 = N.q.z < C.q.w;
        const int bnv0 = N.q.x < C.q.x, bnv1 = N.q.y < C.q.y;
        const int bnv2 = N.q.z < C.q.z, bnv3 = N.q.w < C.q.w;
        const int bnr0 = N.q.y < C.q.x, bnr1 = N.q.z < C.q.y;
        const int bnr2 = N.q.w < C.q.z, bnr3 = N.re  < C.q.w;

        const int s0 = 1 - bl0 - br0 - bu0 - bnv0
                     + (bul0 & bu0 & bl0) + (bu0 & bur0 & br0)
                     + (bl0 & bnl0 & bnv0) + (br0 & bnv0 & bnr0);
        const int s1 = 1 - bl1 - br1 - bu1 - bnv1
                     + (bul1 & bu1 & bl1) + (bu1 & bur1 & br1)
                     + (bl1 & bnl1 & bnv1) + (br1 & bnv1 & bnr1);
        const int s2 = 1 - bl2 - br2 - bu2 - bnv2
                     + (bul2 & bu2 & bl2) + (bu2 & bur2 & br2)
                     + (bl2 & bnl2 & bnv2) + (br2 & bnv2 & bnr2);
        const int s3 = 1 - bl3 - br3 - bu3 - bnv3
                     + (bul3 & bu3 & bl3) + (bu3 & bur3 & br3)
                     + (bl3 & bnl3 & bnv3) + (br3 & bnv3 & bnr3);

        const int t0 = binof(C.q.x), t1 = binof(C.q.y);
        const int t2 = binof(C.q.z), t3 = binof(C.q.w);

        h0[t0 << 8] = (signed char)(h0[t0 << 8] + s0);
        h1[t2 << 8] = (signed char)(h1[t2 << 8] + s2);
        h0[t1 << 8] = (signed char)(h0[t1 << 8] + s1);
        h1[t3 << 8] = (signed char)(h1[t3 << 8] + s3);

        // carry for next row
        pbnl1 = bnl1; pbnl2 = bnl2; pbnl3 = bnl3;
        pbnv0 = bnv0; pbnv1 = bnv1; pbnv2 = bnv2; pbnv3 = bnv3;
        pbnr0 = bnr0; pbnr1 = bnr1; pbnr2 = bnr2;
        ple = C.le; pre = C.re;
        C = N;
    }
    __syncthreads();

    // reduce: 256 i8 slots/bin -> total via dp4a over 64 words (skewed)
    {
        const int bin = tid & 63;
        const int p   = tid >> 6;
        const int* __restrict__ row = (const int*)hist8 + (bin << 6) + (p << 5);
        int sum = 0;
        #pragma unroll 8
        for (int i = 0; i < 32; i++)
            sum = __dp4a(row[(i + bin) & 31], 0x01010101, sum);
        s_red[tid] = sum;
    }
    __syncthreads();
    if (tid < RES)
        g_part[img * (RES * STRIPS) + (tid << 2) + strip] = s_red[tid] + s_red[tid + 64];

    // ---- last block of this image combines, scans, writes out ----
    if (tid == 0) {
        __threadfence();
        int old = atomicAdd(&g_count[img], 1);
        s_last = (old == STRIPS - 1) ? 1 : 0;
    }
    __syncthreads();

    if (s_last && wid == 0) {
        __threadfence();
        const int4* gp = (const int4*)g_part + img * RES;
        int4 p0 = gp[lane];
        int4 p1 = gp[lane + 32];
        int acc = p0.x + p0.y + p0.z + p0.w;
        int b2  = p1.x + p1.y + p1.z + p1.w;

        #pragma unroll
        for (int s = 1; s < 32; s <<= 1) {
            int n = __shfl_up_sync(0xffffffffu, acc, s);
            if (lane >= s) acc += n;
        }
        #pragma unroll
        for (int s = 1; s < 32; s <<= 1) {
            int n = __shfl_up_sync(0xffffffffu, b2, s);
            if (lane >= s) b2 += n;
        }
        b2 += __shfl_sync(0xffffffffu, acc, 31);

        out[img * RES + lane]      = (float)acc;
        out[img * RES + 32 + lane] = (float)b2;

        if (lane == 0) g_count[img] = 0;
    }
}

extern "C" void kernel_launch(void* const* d_in, const int* in_sizes, int n_in,
                              void* d_out, int out_size)
{
    const float* x = (const float*)d_in[0];
    float* out = (float*)d_out;
    ecc_kernel<<<512 * STRIPS, NT>>>(x, out);
}